// round 17
// baseline (speedup 1.0000x reference)
#include <cuda_runtime.h>
#include <cuda_bf16.h>
#include <cstdint>

#define K_BANDS 36
#define EMBED   128
#define MAXF    130
#define KPMAX   144
#define NB_TOT  1025
#define T_LEN   2048
#define B_SZ    8
#define TT      64
#define EPS     1e-5f

// ---- device scratch ----
__device__ float g_S1[K_BANDS * EMBED];
__device__ float g_S2[K_BANDS * EMBED];
// Wg hi/lo bf16x2 pairs, [k][e][KPMAX/2] (k-contig per e), zero-padded
__device__ __align__(16) unsigned g_Bh[K_BANDS * EMBED * (KPMAX / 2)];
__device__ __align__(16) unsigned g_Bl[K_BANDS * EMBED * (KPMAX / 2)];

__device__ __forceinline__ void band_params(int k, int& nb, int& start) {
    if (k < 20)      { nb = 16; start = 16 * k; }
    else if (k < 30) { nb = 32; start = 320 + 32 * (k - 20); }
    else if (k < 35) { nb = 64; start = 640 + 64 * (k - 30); }
    else             { nb = 65; start = 960; }
}

// ================= prep: coalesced via smem tile =================
// grid (36, 8), 128 threads. Block handles 16 e-rows of band k.
__global__ void prep_kernel(const float* __restrict__ W,
                            const float* __restrict__ gamma,
                            const float* __restrict__ beta,
                            const float* __restrict__ bias) {
    const int k = blockIdx.x, q = blockIdx.y;
    const int tid = threadIdx.x;
    int nb, start; band_params(k, nb, start);
    const int f = 2 * nb;
    const int e0 = q * 16;

    __shared__ float tile[16][132];
    __shared__ float gbuf[132], bbuf[132];

    // coalesced load of W rows + gamma/beta
    const float* Wb = W + ((size_t)k * EMBED + e0) * MAXF;
#pragma unroll
    for (int r = 0; r < 16; ++r)
        for (int c = tid; c < MAXF; c += 128)
            tile[r][c] = Wb[r * MAXF + c];
    for (int c = tid; c < MAXF; c += 128) {
        gbuf[c] = gamma[(size_t)k * MAXF + c];
        bbuf[c] = beta [(size_t)k * MAXF + c];
    }
    __syncthreads();

    // S1/S2: 8 lanes per e-row
    {
        int el = tid >> 3, l = tid & 7;
        float s1 = 0.f, s2 = 0.f;
        for (int ff = l; ff < f; ff += 8) {
            float w = tile[el][ff];
            s1 += w * gbuf[ff];
            s2 += w * bbuf[ff];
        }
#pragma unroll
        for (int d = 1; d < 8; d <<= 1) {
            s1 += __shfl_xor_sync(0xFFFFFFFFu, s1, d);
            s2 += __shfl_xor_sync(0xFFFFFFFFu, s2, d);
        }
        if (l == 0) {
            int e = e0 + el;
            g_S1[k * EMBED + e] = s1;
            g_S2[k * EMBED + e] = s2 + bias[k * EMBED + e];
        }
    }

    // hi/lo split, coalesced writes
    for (int idx = tid; idx < 16 * (KPMAX / 2); idx += 128) {
        int el = idx / (KPMAX / 2);
        int p  = idx % (KPMAX / 2);
        int k0 = 2 * p, k1 = 2 * p + 1;
        float w0 = (k0 < f) ? tile[el][k0] * gbuf[k0] : 0.f;
        float w1 = (k1 < f) ? tile[el][k1] * gbuf[k1] : 0.f;
        __nv_bfloat162 h = __floats2bfloat162_rn(w0, w1);
        float2 hf = __bfloat1622float2(h);
        __nv_bfloat162 l = __floats2bfloat162_rn(w0 - hf.x, w1 - hf.y);
        size_t o = ((size_t)k * EMBED + e0 + el) * (KPMAX / 2) + p;
        g_Bh[o] = *(unsigned*)&h;
        g_Bl[o] = *(unsigned*)&l;
    }
}

// ---- ptx helpers ----
__device__ __forceinline__ uint32_t smem_u32(const void* p) {
    uint32_t a;
    asm("{ .reg .u64 t; cvta.to.shared.u64 t, %1; cvt.u32.u64 %0, t; }" : "=r"(a) : "l"(p));
    return a;
}
__device__ __forceinline__ void ldsm_x4_t(uint32_t* r, uint32_t addr) {
    asm volatile("ldmatrix.sync.aligned.m8n8.x4.trans.shared.b16 {%0,%1,%2,%3}, [%4];"
        : "=r"(r[0]), "=r"(r[1]), "=r"(r[2]), "=r"(r[3]) : "r"(addr));
}
__device__ __forceinline__ void mma_bf16(float* c, const uint32_t* a, const uint32_t* b) {
    asm volatile("mma.sync.aligned.m16n8k16.row.col.f32.bf16.bf16.f32 "
        "{%0,%1,%2,%3}, {%4,%5,%6,%7}, {%8,%9}, {%0,%1,%2,%3};"
        : "+f"(c[0]), "+f"(c[1]), "+f"(c[2]), "+f"(c[3])
        : "r"(a[0]), "r"(a[1]), "r"(a[2]), "r"(a[3]), "r"(b[0]), "r"(b[1]));
}

// ---- smem byte offsets ----
// A: [k<=144][t stride 72] bf16 hi/lo; NO B smem (direct LDG fragments)
#define SB_A_HI 0
#define SB_A_LO 20736
#define SB_PS   41472          // 8 x 64 floats
#define SB_PS2  43520
#define SB_MU   45568
#define SB_RS   45824
#define SB_S1   46080
#define SB_S2   46592
#define SM_TOT  47104

__global__ __launch_bounds__(256, 3)
void band_main(const float* __restrict__ spec, float* __restrict__ out) {
    const int kb = 35 - blockIdx.z;          // heavy bands first
    const int b  = blockIdx.y;
    const int t0 = blockIdx.x * TT;
    int nb, start; band_params(kb, nb, start);
    const int f    = 2 * nb;
    const int kpad = (f + 15) & ~15;
    const int nch  = kpad >> 4;

    extern __shared__ __align__(16) char smem[];
    const uint32_t sb = smem_u32(smem);
    const int tid = threadIdx.x;
    const int wid = tid >> 5;
    const int lid = tid & 31;

    // ---- fused stage A + stats: thread owns t-pair, 8-way k split ----
    {
        const int h  = tid >> 5;             // k-group 0..7
        const int t2 = lid * 2;              // t pair base 0..62
        const float* sp4 = spec + (((size_t)b * NB_TOT + start) * T_LEN + t0 + t2) * 2;
        float sA = 0.f, s2A = 0.f, sB = 0.f, s2B = 0.f;
        for (int j = h; j < nb; j += 8) {
            float4 v = *(const float4*)(sp4 + (size_t)j * T_LEN * 2);
            sA += v.x + v.y;  s2A = fmaf(v.x, v.x, s2A); s2A = fmaf(v.y, v.y, s2A);
            sB += v.z + v.w;  s2B = fmaf(v.z, v.z, s2B); s2B = fmaf(v.w, v.w, s2B);
            __nv_bfloat162 h0 = __floats2bfloat162_rn(v.x, v.z);
            float2 h0f = __bfloat1622float2(h0);
            __nv_bfloat162 l0 = __floats2bfloat162_rn(v.x - h0f.x, v.z - h0f.y);
            __nv_bfloat162 h1 = __floats2bfloat162_rn(v.y, v.w);
            float2 h1f = __bfloat1622float2(h1);
            __nv_bfloat162 l1 = __floats2bfloat162_rn(v.y - h1f.x, v.w - h1f.y);
            int o0 = ((2 * j)     * 72 + t2) * 2;
            int o1 = ((2 * j + 1) * 72 + t2) * 2;
            *(__nv_bfloat162*)(smem + SB_A_HI + o0) = h0;
            *(__nv_bfloat162*)(smem + SB_A_LO + o0) = l0;
            *(__nv_bfloat162*)(smem + SB_A_HI + o1) = h1;
            *(__nv_bfloat162*)(smem + SB_A_LO + o1) = l1;
        }
        ((float*)(smem + SB_PS))[h * 64 + t2]      = sA;
        ((float*)(smem + SB_PS))[h * 64 + t2 + 1]  = sB;
        ((float*)(smem + SB_PS2))[h * 64 + t2]     = s2A;
        ((float*)(smem + SB_PS2))[h * 64 + t2 + 1] = s2B;
    }
    // zero A pad rows [f, kpad): 36 u32 per row per buffer
    for (int i = tid; i < (kpad - f) * 36; i += 256) {
        int r = f + i / 36, c4 = i % 36;
        *(unsigned*)(smem + SB_A_HI + r * 144 + c4 * 4) = 0u;
        *(unsigned*)(smem + SB_A_LO + r * 144 + c4 * 4) = 0u;
    }
    __syncthreads();

    // ---- finalize stats | stage S1/S2 ----
    if (tid < 64) {
        int t = tid;
        float s = 0.f, s2 = 0.f;
#pragma unroll
        for (int h = 0; h < 8; ++h) {
            s  += ((float*)(smem + SB_PS))[h * 64 + t];
            s2 += ((float*)(smem + SB_PS2))[h * 64 + t];
        }
        float inv_f = 1.0f / (float)f;
        float m = s * inv_f;
        float var = fmaxf(s2 * inv_f - m * m, 0.f);
        ((float*)(smem + SB_MU))[t] = m;
        ((float*)(smem + SB_RS))[t] = rsqrtf(var + EPS);
    } else if (tid < 192) {
        int e = tid - 64;
        ((float*)(smem + SB_S1))[e] = g_S1[kb * EMBED + e];
        ((float*)(smem + SB_S2))[e] = g_S2[kb * EMBED + e];
    }
    __syncthreads();   // MU/RS/S1/S2 visible; NO more barriers after this

    // ---- MMA mainloop: warp tile 32t x 32e, B fragments DIRECT from gmem ----
    const int wm = wid & 1, wn = wid >> 1;
    const int tb = wm * 32, n0 = wn * 32;
    const int lrow  = (lid & 7) + ((lid >> 4) << 3);
    const int lcol8 = ((lid >> 3) & 1) << 3;

    float acc[2][4][4];
#pragma unroll
    for (int m = 0; m < 2; ++m)
#pragma unroll
        for (int g = 0; g < 4; ++g)
#pragma unroll
            for (int q = 0; q < 4; ++q) acc[m][g][q] = 0.f;

    // per-lane B fragment base pointers (b0 of n-block gg=0, chunk 0)
    const size_t boff = ((size_t)kb * EMBED + n0 + (lid >> 2)) * (KPMAX / 2) + (lid & 3);
    const unsigned* __restrict__ pBh = g_Bh + boff;
    const unsigned* __restrict__ pBl = g_Bl + boff;

    const uint32_t adA = sb + SB_A_HI + (lrow * 72 + tb + lcol8) * 2;  // + m*32 + c*2304

    for (int c = 0; c < nch; ++c) {
        // B frags: 16 independent LDG.32 (L2-hot), no barriers anywhere
        uint32_t bh[2][4], bl[2][4];
#pragma unroll
        for (int gg = 0; gg < 2; ++gg) {
            const unsigned* qh = pBh + gg * 16 * (KPMAX / 2) + 8 * c;
            const unsigned* ql = pBl + gg * 16 * (KPMAX / 2) + 8 * c;
            bh[gg][0] = qh[0];   bh[gg][1] = qh[4];
            bh[gg][2] = qh[576]; bh[gg][3] = qh[580];
            bl[gg][0] = ql[0];   bl[gg][1] = ql[4];
            bl[gg][2] = ql[576]; bl[gg][3] = ql[580];
        }

        uint32_t ah[2][4], al[2][4];
        const uint32_t aA = adA + c * 2304;           // c*16 rows * 72 * 2B
#pragma unroll
        for (int m = 0; m < 2; ++m) {
            ldsm_x4_t(ah[m], aA + m * 32);
            ldsm_x4_t(al[m], aA + m * 32 + (SB_A_LO - SB_A_HI));
        }

        // 3 passes, 8 distinct accumulators per pass
#pragma unroll
        for (int m = 0; m < 2; ++m)
#pragma unroll
            for (int gg = 0; gg < 2; ++gg) {
                mma_bf16(acc[m][2 * gg],     ah[m], bh[gg]);
                mma_bf16(acc[m][2 * gg + 1], ah[m], bh[gg] + 2);
            }
#pragma unroll
        for (int m = 0; m < 2; ++m)
#pragma unroll
            for (int gg = 0; gg < 2; ++gg) {
                mma_bf16(acc[m][2 * gg],     al[m], bh[gg]);
                mma_bf16(acc[m][2 * gg + 1], al[m], bh[gg] + 2);
            }
#pragma unroll
        for (int m = 0; m < 2; ++m)
#pragma unroll
            for (int gg = 0; gg < 2; ++gg) {
                mma_bf16(acc[m][2 * gg],     ah[m], bl[gg]);
                mma_bf16(acc[m][2 * gg + 1], ah[m], bl[gg] + 2);
            }
    }

    // ---- epilogue: y = rs*(acc - mu*S1) + S2, direct streaming STG ----
    {
        const float* mus = (const float*)(smem + SB_MU);
        const float* rss = (const float*)(smem + SB_RS);
        const float* s1s = (const float*)(smem + SB_S1);
        const float* s2s = (const float*)(smem + SB_S2);
        const size_t estr = (size_t)K_BANDS * T_LEN;
        float* ob = out + (((size_t)b * EMBED) * K_BANDS + kb) * T_LEN + t0;

#pragma unroll
        for (int m = 0; m < 2; ++m) {
            int t1 = tb + m * 16 + (lid >> 2);
            float mu0 = mus[t1],     rs0 = rss[t1];
            float mu1 = mus[t1 + 8], rs1 = rss[t1 + 8];
#pragma unroll
            for (int g = 0; g < 4; ++g) {
                int e0 = n0 + g * 8 + ((lid & 3) << 1);
                float2 s1 = *(const float2*)&s1s[e0];
                float2 s2 = *(const float2*)&s2s[e0];
                float* a4 = acc[m][g];
                float* p0 = ob + (size_t)e0 * estr + t1;
                float* p1 = p0 + estr;
                __stcs(p0,     fmaf(rs0, fmaf(-mu0, s1.x, a4[0]), s2.x));
                __stcs(p1,     fmaf(rs0, fmaf(-mu0, s1.y, a4[1]), s2.y));
                __stcs(p0 + 8, fmaf(rs1, fmaf(-mu1, s1.x, a4[2]), s2.x));
                __stcs(p1 + 8, fmaf(rs1, fmaf(-mu1, s1.y, a4[3]), s2.y));
            }
        }
    }
}

extern "C" void kernel_launch(void* const* d_in, const int* in_sizes, int n_in,
                              void* d_out, int out_size) {
    const float* spec  = (const float*)d_in[0];
    const float* gamma = (const float*)d_in[1];
    const float* beta  = (const float*)d_in[2];
    const float* W     = (const float*)d_in[3];
    const float* bias  = (const float*)d_in[4];
    float* out = (float*)d_out;

    prep_kernel<<<dim3(K_BANDS, 8), 128>>>(W, gamma, beta, bias);

    cudaFuncSetAttribute(band_main, cudaFuncAttributeMaxDynamicSharedMemorySize, SM_TOT);
    dim3 grid(T_LEN / TT, B_SZ, K_BANDS);
    band_main<<<grid, 256, SM_TOT>>>(spec, out);
}